// round 1
// baseline (speedup 1.0000x reference)
#include <cuda_runtime.h>
#include <cuda_bf16.h>
#include <cstdint>
#include <cstdio>

#define TT 2048
#define BB 32
#define HH 512
#define GG 2048   // 4*H
#define RG 128    // recurrence CTAs
#define RT 256    // recurrence threads/CTA

// ---------------- device scratch (static globals; no allocation) ----------------
__device__ float  g_ix[(size_t)TT * GG * BB];   // input projections [t][gate][b] (512 MB)
__device__ float  g_hs[(size_t)TT * BB * HH];   // per-step h outputs [t][b][k]   (128 MB)
__device__ float2 g_hbuf[2][HH / 2][BB];        // h double buffer, (k-pair, b) packed
__device__ int    g_cnt[2];                     // per-layer step counters

// ---------------- helpers ----------------
__device__ __forceinline__ unsigned long long fma2v(unsigned long long a,
                                                    unsigned long long b,
                                                    unsigned long long c) {
    unsigned long long d;
    asm("fma.rn.f32x2 %0, %1, %2, %3;" : "=l"(d) : "l"(a), "l"(b), "l"(c));
    return d;
}
__device__ __forceinline__ float2 unpack2(unsigned long long v) {
    float2 f;
    asm("mov.b64 {%0, %1}, %2;" : "=f"(f.x), "=f"(f.y) : "l"(v));
    return f;
}
__device__ __forceinline__ int ld_acq(const int* p) {
    int v;
    asm volatile("ld.acquire.gpu.b32 %0, [%1];" : "=r"(v) : "l"(p) : "memory");
    return v;
}

// ---------------- input-projection GEMM ----------------
// C[token=(t,b), n] = sum_k A[token,k] * W[n,k] + bi[n] + bh[n]
// A row = emb[x[b,t]] (use_gather) or g_hs[token].
// Output layout: g_ix[t][n][b].
__global__ __launch_bounds__(256) void gemm_proj(
    const int* __restrict__ x, const float* __restrict__ emb,
    const float* __restrict__ W, const float* __restrict__ bi,
    const float* __restrict__ bh, int use_gather)
{
    __shared__ __align__(16) float2 Ash[16 * 64];   // [k2][m]
    __shared__ __align__(16) float2 Wsh[16 * 64];   // [k2][n]
    __shared__ const float* rowptr[64];

    int tid = threadIdx.x;
    int n0 = blockIdx.x * 64, m0 = blockIdx.y * 64;

    if (tid < 64) {
        int mg = m0 + tid;
        const float* p;
        if (use_gather) {
            int t = mg >> 5, b = mg & 31;
            p = emb + (size_t)x[b * TT + t] * HH;
        } else {
            p = g_hs + (size_t)mg * HH;
        }
        rowptr[tid] = p;
    }
    __syncthreads();

    unsigned long long acc[16];
#pragma unroll
    for (int i = 0; i < 16; i++) acc[i] = 0ULL;

    int ty = tid >> 4, tx = tid & 15;
    int ty4 = ty * 4, tx4 = tx * 4;

    for (int kt = 0; kt < 16; ++kt) {
        int k0 = kt * 32;
        __syncthreads();   // WAR guard for previous compute
#pragma unroll
        for (int u = 0; u < 2; u++) {
            int v = tid + u * 256;
            int row = v >> 3, kq = v & 7;
            float4 a = *(const float4*)(rowptr[row] + k0 + kq * 4);
            Ash[(kq * 2)     * 64 + row] = make_float2(a.x, a.y);
            Ash[(kq * 2 + 1) * 64 + row] = make_float2(a.z, a.w);
            float4 wv = *(const float4*)(W + (size_t)(n0 + row) * HH + k0 + kq * 4);
            Wsh[(kq * 2)     * 64 + row] = make_float2(wv.x, wv.y);
            Wsh[(kq * 2 + 1) * 64 + row] = make_float2(wv.z, wv.w);
        }
        __syncthreads();
#pragma unroll
        for (int k2 = 0; k2 < 16; k2++) {
            ulonglong2 a01 = *(const ulonglong2*)&Ash[k2 * 64 + ty4];
            ulonglong2 a23 = *(const ulonglong2*)&Ash[k2 * 64 + ty4 + 2];
            ulonglong2 w01 = *(const ulonglong2*)&Wsh[k2 * 64 + tx4];
            ulonglong2 w23 = *(const ulonglong2*)&Wsh[k2 * 64 + tx4 + 2];
            unsigned long long av[4] = {a01.x, a01.y, a23.x, a23.y};
            unsigned long long wv[4] = {w01.x, w01.y, w23.x, w23.y};
#pragma unroll
            for (int i = 0; i < 4; i++)
#pragma unroll
                for (int j = 0; j < 4; j++)
                    acc[i * 4 + j] = fma2v(av[i], wv[j], acc[i * 4 + j]);
        }
    }

#pragma unroll
    for (int i = 0; i < 4; i++) {
        int mg = m0 + ty4 + i;
        int t = mg >> 5, b = mg & 31;
#pragma unroll
        for (int j = 0; j < 4; j++) {
            int ng = n0 + tx4 + j;
            float2 p = unpack2(acc[i * 4 + j]);
            g_ix[((size_t)t * GG + ng) * BB + b] = p.x + p.y + bi[ng] + bh[ng];
        }
    }
}

// ---------------- persistent recurrence ----------------
// G=128 CTAs, CTA blockIdx.x owns hidden units [U0, U0+4). Gate rows r = gi*4+ui.
// Per step: gates = ix[t] + h_{t-1} @ Whh^T (slice); LSTM cell; publish h.
__global__ __launch_bounds__(RT, 1) void recur_kernel(const float* __restrict__ Whh, int layer)
{
    extern __shared__ char smem[];
    float2* Wsh = (float2*)smem;                              // [256 k2][16 r]  32KB
    float*  red = (float*)(smem + 32768);                     // [8 w][16 r][32 b] 16KB
    float*  gsh = (float*)(smem + 32768 + 16384);             // [16 r][32 b]   2KB
    float*  csh = (float*)(smem + 32768 + 16384 + 2048);      // [4 u][32 b]

    int* cnt = &g_cnt[layer];
    int tid = threadIdx.x;
    int U0 = blockIdx.x * 4;
    int w = tid >> 5, lane = tid & 31;

    // Load transposed Whh slice: Wsh[k2*16 + r] = (W[grow][2k2], W[grow][2k2+1])
    for (int v = tid; v < 256 * 16; v += RT) {
        int k2 = v >> 4, r = v & 15;
        int grow = (r >> 2) * HH + U0 + (r & 3);
        const float* wr = Whh + (size_t)grow * HH + 2 * k2;
        Wsh[v] = make_float2(wr[0], wr[1]);
    }
    // Zero our slice of h buffer (parity 0) and c-state
    if (tid < 128) {
        int ui = tid >> 5, b = tid & 31;
        int k = U0 + ui;
        ((float*)&g_hbuf[0][0][0])[(size_t)(k >> 1) * 64 + b * 2 + (k & 1)] = 0.f;
        csh[ui * 32 + b] = 0.f;
    }
    __syncthreads();
    if (tid == 0) { __threadfence(); atomicAdd(cnt, 1); }

    int r0 = w, r1 = w + 8, b = lane;
    int grow0 = (r0 >> 2) * HH + U0 + (r0 & 3);
    int grow1 = (r1 >> 2) * HH + U0 + (r1 & 3);

    for (int t = 0; t < TT; ++t) {
        // Prefetch ix (independent of h) before the spin
        float ixv0 = g_ix[((size_t)t * GG + grow0) * BB + b];
        float ixv1 = g_ix[((size_t)t * GG + grow1) * BB + b];

        if (tid == 0) {
            int target = (t + 1) * RG;
            while (ld_acq(cnt) < target) {}
        }
        __syncthreads();

        int par = t & 1;
        const unsigned long long* hb = (const unsigned long long*)&g_hbuf[par][0][0];
        unsigned long long hreg[32];
#pragma unroll
        for (int i = 0; i < 32; i++) hreg[i] = hb[(size_t)(w * 32 + i) * 32 + lane];

        unsigned long long acc[16];
#pragma unroll
        for (int r = 0; r < 16; r++) acc[r] = 0ULL;
#pragma unroll
        for (int i = 0; i < 32; i++) {
            unsigned long long hv = hreg[i];
            const ulonglong2* wp = (const ulonglong2*)(Wsh + (size_t)(w * 32 + i) * 16);
#pragma unroll
            for (int r = 0; r < 16; r += 2) {
                ulonglong2 ww = wp[r >> 1];
                acc[r]     = fma2v(ww.x, hv, acc[r]);
                acc[r + 1] = fma2v(ww.y, hv, acc[r + 1]);
            }
        }
#pragma unroll
        for (int r = 0; r < 16; r++) {
            float2 p = unpack2(acc[r]);
            red[(w * 16 + r) * 32 + lane] = p.x + p.y;
        }
        __syncthreads();

        // cross-warp reduction (+ ix with both biases already folded in)
        float s0 = ixv0, s1 = ixv1;
#pragma unroll
        for (int ww2 = 0; ww2 < 8; ww2++) {
            s0 += red[(ww2 * 16 + r0) * 32 + b];
            s1 += red[(ww2 * 16 + r1) * 32 + b];
        }
        gsh[r0 * 32 + b] = s0;
        gsh[r1 * 32 + b] = s1;
        __syncthreads();

        if (tid < 128) {
            int ui = tid >> 5; int bb = tid & 31;
            float gi = gsh[(ui)      * 32 + bb];
            float gf = gsh[(4 + ui)  * 32 + bb];
            float gg = gsh[(8 + ui)  * 32 + bb];
            float go = gsh[(12 + ui) * 32 + bb];
            float si = 1.f / (1.f + expf(-gi));
            float sf = 1.f / (1.f + expf(-gf));
            float so = 1.f / (1.f + expf(-go));
            float c  = sf * csh[ui * 32 + bb] + si * tanhf(gg);
            float h  = so * tanhf(c);
            csh[ui * 32 + bb] = c;
            int k = U0 + ui;
            ((float*)&g_hbuf[(t + 1) & 1][0][0])[(size_t)(k >> 1) * 64 + bb * 2 + (k & 1)] = h;
            g_hs[((size_t)t * BB + bb) * HH + k] = h;
        }
        __syncthreads();
        if (tid == 0) { __threadfence(); atomicAdd(cnt, 1); }
    }
}

// ---------------- head: logits + log-softmax + NLL ----------------
__global__ void head_kernel(const float* __restrict__ fcw, const float* __restrict__ fcb,
                            const int* __restrict__ labels, float* __restrict__ out, int out_size)
{
    __shared__ float lg[128];
    __shared__ float pl[32];
    int tid = threadIdx.x;      // 128
    int b = tid >> 2, c = tid & 3;
    const float* h = g_hs + ((size_t)(TT - 1) * BB + b) * HH;
    const float* wr = fcw + c * HH;
    float acc = 0.f;
#pragma unroll 8
    for (int k = 0; k < HH; k += 4) {
        float4 hv = *(const float4*)(h + k);
        float4 wv = *(const float4*)(wr + k);
        acc += hv.x * wv.x + hv.y * wv.y + hv.z * wv.z + hv.w * wv.w;
    }
    lg[b * 4 + c] = acc + fcb[c];
    __syncthreads();
    if (tid < 32) {
        float l0 = lg[tid * 4], l1 = lg[tid * 4 + 1], l2 = lg[tid * 4 + 2], l3 = lg[tid * 4 + 3];
        float m = fmaxf(fmaxf(l0, l1), fmaxf(l2, l3));
        float lse = m + logf(expf(l0 - m) + expf(l1 - m) + expf(l2 - m) + expf(l3 - m));
        int lab = labels[tid];
        pl[tid] = lg[tid * 4 + lab] - lse;
    }
    __syncthreads();
    if (tid == 0) {
        float s = 0.f;
        for (int i = 0; i < 32; i++) s += pl[i];
        float loss = -s / 32.f;
        if (out_size == 128) {
            for (int i = 0; i < 128; i++) out[i] = lg[i];
        } else {
            out[0] = loss;
            int n = out_size - 1; if (n > 128) n = 128;
            for (int i = 0; i < n; i++) out[1 + i] = lg[i];
            for (int i = 129; i < out_size; i++) out[i] = 0.f;
        }
    }
}

__global__ void zero_kernel() { g_cnt[0] = 0; g_cnt[1] = 0; }

// ---------------- launch ----------------
extern "C" void kernel_launch(void* const* d_in, const int* in_sizes, int n_in,
                              void* d_out, int out_size)
{
    const int*   x      = (const int*)d_in[0];
    const int*   labels = (const int*)d_in[1];
    const float* emb    = (const float*)d_in[2];
    const float* Wih    = (const float*)d_in[3];
    const float* Whh    = (const float*)d_in[4];
    const float* bih    = (const float*)d_in[5];
    const float* bhh    = (const float*)d_in[6];
    const float* fcw    = (const float*)d_in[7];
    const float* fcb    = (const float*)d_in[8];
    float* out = (float*)d_out;

    cudaFuncSetAttribute(recur_kernel, cudaFuncAttributeMaxDynamicSharedMemorySize, 51712);

    zero_kernel<<<1, 1>>>();

    dim3 g1(GG / 64, (TT * BB) / 64);   // (32, 1024)
    // layer 0
    gemm_proj<<<g1, 256>>>(x, emb, Wih, bih, bhh, 1);
    recur_kernel<<<RG, RT, 51712>>>(Whh, 0);
    // layer 1
    gemm_proj<<<g1, 256>>>(x, emb, Wih + (size_t)GG * HH, bih + GG, bhh + GG, 0);
    recur_kernel<<<RG, RT, 51712>>>(Whh + (size_t)GG * HH, 1);
    // head
    head_kernel<<<1, 128>>>(fcw, fcb, labels, out, out_size);
}